// round 2
// baseline (speedup 1.0000x reference)
#include <cuda_runtime.h>
#include <math.h>

// ---------------------------------------------------------------------------
// BranchedAttention: B=4, Q=S=1024, H=1024, N_HEADS=8, K_SIZE=V_SIZE=128
// Output: y [4,1024,1024] followed by attn [32,1024,1024] (float32)
// ---------------------------------------------------------------------------

#define NHEADS 8
#define BATCH  4
#define QLEN   1024
#define SLEN   1024
#define HSIZE  1024
#define KSIZE  128
#define MROWS  (BATCH * QLEN)           // 4096
#define HEAD_MK ((size_t)MROWS * KSIZE) // 524288
#define BQ_MK  ((size_t)QLEN * KSIZE)   // 131072 (per (n,b) slice of qh/kh/vh)

// Scratch (device globals; allocation-free)
static __device__ float g_qh[(size_t)NHEADS * MROWS * KSIZE];
static __device__ float g_kh[(size_t)NHEADS * MROWS * KSIZE];
static __device__ float g_vh[(size_t)NHEADS * MROWS * KSIZE];
static __device__ float g_ov[(size_t)NHEADS * MROWS * KSIZE];
static __device__ float g_hidden[(size_t)MROWS * 2048];
static __device__ float g_acc[(size_t)MROWS * HSIZE];
static __device__ float g_gates[16];   // [0..7] = softmax(k_gate), [8..15] = softmax(a_gate)

// ---------------------------------------------------------------------------
// Gate softmax (8 elements each)
// ---------------------------------------------------------------------------
__global__ void gates_kernel(const float* __restrict__ kg, const float* __restrict__ ag) {
    if (threadIdx.x == 0) {
        float mk = -1e30f, ma = -1e30f;
        for (int i = 0; i < 8; i++) { mk = fmaxf(mk, kg[i]); ma = fmaxf(ma, ag[i]); }
        float ek[8], ea[8], sk = 0.f, sa = 0.f;
        for (int i = 0; i < 8; i++) {
            ek[i] = expf(kg[i] - mk); sk += ek[i];
            ea[i] = expf(ag[i] - ma); sa += ea[i];
        }
        for (int i = 0; i < 8; i++) {
            g_gates[i]     = ek[i] / sk;
            g_gates[8 + i] = ea[i] / sa;
        }
    }
}

// ---------------------------------------------------------------------------
// Tiled SGEMM: C = op(A[M,K] * B) per batch-z, row-major.
// TRANSB=false: B is [K,N]. TRANSB=true: B is [N,K].
// EPI 0: C = alpha_imm * AB
// EPI 1: C = (*alpha_ptr) * AB
// EPI 2: C += selu(AB + bias[col]) * (*alpha_ptr)
// Tile 128x128x8, 256 threads, 8x8 micro-tile. All dims divide evenly.
// ---------------------------------------------------------------------------
template<bool TRANSB, int EPI>
__global__ void __launch_bounds__(256)
gemm_kernel(const float* __restrict__ A, const float* __restrict__ B,
            float* __restrict__ C,
            int K, int lda, int ldb, int ldc,
            long long sA, long long sB, long long sC,
            float alpha_imm, const float* __restrict__ alpha_ptr,
            const float* __restrict__ bias)
{
    A += (long long)blockIdx.z * sA;
    B += (long long)blockIdx.z * sB;
    C += (long long)blockIdx.z * sC;

    __shared__ float As[8][132];
    __shared__ float Bs[8][132];

    const int t  = threadIdx.x;
    const int tx = t & 15;        // 0..15  -> 8 output cols each
    const int ty = t >> 4;        // 0..15  -> 8 output rows each
    const int m0 = blockIdx.y * 128;
    const int n0 = blockIdx.x * 128;

    // A tile load: 128 rows x 8 k; thread -> (row = t>>1, k = (t&1)*4), float4 along k
    const int a_r = t >> 1;
    const int a_k = (t & 1) << 2;
    // B tile load (NN): 8 k x 128 n; thread -> (k = t>>5, n = (t&31)*4)
    const int b_k = t >> 5;
    const int b_n = (t & 31) << 2;

    float acc[8][8];
#pragma unroll
    for (int i = 0; i < 8; i++)
#pragma unroll
        for (int j = 0; j < 8; j++) acc[i][j] = 0.f;

    for (int k0 = 0; k0 < K; k0 += 8) {
        float4 av = *(const float4*)(A + (size_t)(m0 + a_r) * lda + k0 + a_k);
        As[a_k + 0][a_r] = av.x;
        As[a_k + 1][a_r] = av.y;
        As[a_k + 2][a_r] = av.z;
        As[a_k + 3][a_r] = av.w;
        if (TRANSB) {
            // B is [N,K]: thread -> (n = t>>1, k = (t&1)*4), transpose-store
            float4 bv = *(const float4*)(B + (size_t)(n0 + a_r) * ldb + k0 + a_k);
            Bs[a_k + 0][a_r] = bv.x;
            Bs[a_k + 1][a_r] = bv.y;
            Bs[a_k + 2][a_r] = bv.z;
            Bs[a_k + 3][a_r] = bv.w;
        } else {
            float4 bv = *(const float4*)(B + (size_t)(k0 + b_k) * ldb + n0 + b_n);
            *(float4*)&Bs[b_k][b_n] = bv;
        }
        __syncthreads();

#pragma unroll
        for (int kk = 0; kk < 8; kk++) {
            float4 a0 = *(const float4*)&As[kk][ty << 3];
            float4 a1 = *(const float4*)&As[kk][(ty << 3) + 4];
            float4 b0 = *(const float4*)&Bs[kk][tx << 3];
            float4 b1 = *(const float4*)&Bs[kk][(tx << 3) + 4];
            float ar[8] = {a0.x, a0.y, a0.z, a0.w, a1.x, a1.y, a1.z, a1.w};
            float br[8] = {b0.x, b0.y, b0.z, b0.w, b1.x, b1.y, b1.z, b1.w};
#pragma unroll
            for (int i = 0; i < 8; i++)
#pragma unroll
                for (int j = 0; j < 8; j++)
                    acc[i][j] += ar[i] * br[j];
        }
        __syncthreads();
    }

    const float alpha = (EPI == 0) ? alpha_imm : *alpha_ptr;
    const int row = m0 + (ty << 3);
    const int col = n0 + (tx << 3);
#pragma unroll
    for (int i = 0; i < 8; i++) {
        float* c = C + (size_t)(row + i) * ldc + col;
        if (EPI == 2) {
#pragma unroll
            for (int j = 0; j < 8; j++) {
                float val = acc[i][j] + bias[col + j];
                val = (val > 0.f) ? 1.0507009873554805f * val
                                  : 1.0507009873554805f * 1.6732632423543772f * (expf(val) - 1.f);
                c[j] += val * alpha;
            }
        } else {
            float4 v0 = make_float4(alpha * acc[i][0], alpha * acc[i][1],
                                    alpha * acc[i][2], alpha * acc[i][3]);
            float4 v1 = make_float4(alpha * acc[i][4], alpha * acc[i][5],
                                    alpha * acc[i][6], alpha * acc[i][7]);
            *(float4*)(c + 0) = v0;
            *(float4*)(c + 4) = v1;
        }
    }
}

// ---------------------------------------------------------------------------
// Block reductions (256 threads, 8 warps)
// ---------------------------------------------------------------------------
__device__ __forceinline__ float warp_sum(float v) {
#pragma unroll
    for (int o = 16; o > 0; o >>= 1) v += __shfl_xor_sync(0xffffffffu, v, o);
    return v;
}
__device__ __forceinline__ float warp_max(float v) {
#pragma unroll
    for (int o = 16; o > 0; o >>= 1) v = fmaxf(v, __shfl_xor_sync(0xffffffffu, v, o));
    return v;
}
__device__ __forceinline__ float block_sum(float v, float* sh) {
    v = warp_sum(v);
    __syncthreads();
    if ((threadIdx.x & 31) == 0) sh[threadIdx.x >> 5] = v;
    __syncthreads();
    if (threadIdx.x < 32) {
        float x = (threadIdx.x < 8) ? sh[threadIdx.x] : 0.f;
        x = warp_sum(x);
        if (threadIdx.x == 0) sh[0] = x;
    }
    __syncthreads();
    return sh[0];
}
__device__ __forceinline__ float block_max(float v, float* sh) {
    v = warp_max(v);
    __syncthreads();
    if ((threadIdx.x & 31) == 0) sh[threadIdx.x >> 5] = v;
    __syncthreads();
    if (threadIdx.x < 32) {
        float x = (threadIdx.x < 8) ? sh[threadIdx.x] : -1e30f;
        x = warp_max(x);
        if (threadIdx.x == 0) sh[0] = x;
    }
    __syncthreads();
    return sh[0];
}

// ---------------------------------------------------------------------------
// Row softmax over 1024 elements, in place. One block per row.
// ---------------------------------------------------------------------------
__global__ void __launch_bounds__(256) softmax_kernel(float* __restrict__ attn) {
    __shared__ float sh[8];
    float* row = attn + (size_t)blockIdx.x * SLEN;
    const int t = threadIdx.x;
    float4 v = *((float4*)row + t);
    float m = fmaxf(fmaxf(v.x, v.y), fmaxf(v.z, v.w));
    m = block_max(m, sh);
    v.x = __expf(v.x - m);
    v.y = __expf(v.y - m);
    v.z = __expf(v.z - m);
    v.w = __expf(v.w - m);
    float s = v.x + v.y + v.z + v.w;
    s = block_sum(s, sh);
    const float inv = 1.0f / s;
    v.x *= inv; v.y *= inv; v.z *= inv; v.w *= inv;
    *((float4*)row + t) = v;
}

// ---------------------------------------------------------------------------
// LayerNorm(acc + residual). One block per row of 1024.
// ---------------------------------------------------------------------------
__global__ void __launch_bounds__(256)
ln_kernel(const float* __restrict__ acc, const float* __restrict__ resid,
          const float* __restrict__ gamma, const float* __restrict__ beta,
          float* __restrict__ y)
{
    __shared__ float sh[8];
    const size_t off = (size_t)blockIdx.x * HSIZE;
    const int t = threadIdx.x;
    float4 a = *((const float4*)(acc + off) + t);
    float4 r = *((const float4*)(resid + off) + t);
    float4 x = make_float4(a.x + r.x, a.y + r.y, a.z + r.z, a.w + r.w);
    float s  = x.x + x.y + x.z + x.w;
    float ss = x.x * x.x + x.y * x.y + x.z * x.z + x.w * x.w;
    s = block_sum(s, sh);
    __syncthreads();
    ss = block_sum(ss, sh);
    const float mu   = s * (1.0f / HSIZE);
    const float var  = ss * (1.0f / HSIZE) - mu * mu;
    const float rstd = rsqrtf(var + 1e-6f);
    float4 g = *((const float4*)gamma + t);
    float4 b = *((const float4*)beta + t);
    float4 o;
    o.x = (x.x - mu) * rstd * g.x + b.x;
    o.y = (x.y - mu) * rstd * g.y + b.y;
    o.z = (x.z - mu) * rstd * g.z + b.z;
    o.w = (x.w - mu) * rstd * g.w + b.w;
    *((float4*)(y + off) + t) = o;
}

// ---------------------------------------------------------------------------
// Zero fill (float4 per thread)
// ---------------------------------------------------------------------------
__global__ void zero_kernel(float4* __restrict__ p) {
    p[(size_t)blockIdx.x * blockDim.x + threadIdx.x] = make_float4(0.f, 0.f, 0.f, 0.f);
}

// ---------------------------------------------------------------------------
// Launcher
// ---------------------------------------------------------------------------
extern "C" void kernel_launch(void* const* d_in, const int* in_sizes, int n_in,
                              void* d_out, int out_size)
{
    const float* q      = (const float*)d_in[0];
    const float* k      = (const float*)d_in[1];
    const float* v      = (const float*)d_in[2];
    const float* w_q    = (const float*)d_in[3];
    const float* w_k    = (const float*)d_in[4];
    const float* w_v    = (const float*)d_in[5];
    const float* w_o    = (const float*)d_in[6];
    const float* a_gate = (const float*)d_in[7];
    const float* k_gate = (const float*)d_in[8];
    const float* fc_w   = (const float*)d_in[9];
    const float* fc_b   = (const float*)d_in[10];
    const float* ln_g   = (const float*)d_in[11];
    const float* ln_b   = (const float*)d_in[12];

    float* out_y    = (float*)d_out;
    float* out_attn = out_y + (size_t)BATCH * QLEN * HSIZE;   // 4,194,304

    float *qh, *kh, *vh, *ov, *hidden, *acc, *gates;
    cudaGetSymbolAddress((void**)&qh,     g_qh);
    cudaGetSymbolAddress((void**)&kh,     g_kh);
    cudaGetSymbolAddress((void**)&vh,     g_vh);
    cudaGetSymbolAddress((void**)&ov,     g_ov);
    cudaGetSymbolAddress((void**)&hidden, g_hidden);
    cudaGetSymbolAddress((void**)&acc,    g_acc);
    cudaGetSymbolAddress((void**)&gates,  g_gates);

    const dim3 blk(256);

    // gate softmaxes
    gates_kernel<<<1, 32>>>(k_gate, a_gate);

    // per-head projections: [4096,1024] @ [1024,128] per head (z = head)
    gemm_kernel<false, 0><<<dim3(1, 32, 8), blk>>>(
        q, w_q, qh, HSIZE, HSIZE, KSIZE, KSIZE,
        0LL, (long long)HSIZE * KSIZE, (long long)HEAD_MK, 1.f, nullptr, nullptr);
    gemm_kernel<false, 0><<<dim3(1, 32, 8), blk>>>(
        k, w_k, kh, HSIZE, HSIZE, KSIZE, KSIZE,
        0LL, (long long)HSIZE * KSIZE, (long long)HEAD_MK, 1.f, nullptr, nullptr);
    gemm_kernel<false, 0><<<dim3(1, 32, 8), blk>>>(
        v, w_v, vh, HSIZE, HSIZE, KSIZE, KSIZE,
        0LL, (long long)HSIZE * KSIZE, (long long)HEAD_MK, 1.f, nullptr, nullptr);

    // scores: qh[z] [1024,128] @ kh[z]^T -> attn_raw [1024,1024], z = n*4+b (32)
    gemm_kernel<true, 0><<<dim3(8, 8, 32), blk>>>(
        qh, kh, out_attn, KSIZE, KSIZE, KSIZE, SLEN,
        (long long)BQ_MK, (long long)BQ_MK, (long long)QLEN * SLEN,
        0.08838834764831843f, nullptr, nullptr);

    // softmax over S, in place in the attn output region
    softmax_kernel<<<NHEADS * BATCH * QLEN, 256>>>(out_attn);

    // ov = attn @ vh : [1024,1024] @ [1024,128] per z (32)
    gemm_kernel<false, 0><<<dim3(1, 8, 32), blk>>>(
        out_attn, vh, ov, SLEN, SLEN, KSIZE, KSIZE,
        (long long)QLEN * SLEN, (long long)BQ_MK, (long long)BQ_MK,
        1.f, nullptr, nullptr);

    // zero the cross-head accumulator (4096*1024 floats = 1,048,576 float4)
    zero_kernel<<<4096, 256>>>((float4*)acc);

    // per-head: hidden = (ov[n] @ w_o[n]) * softmax(k_gate)[n]
    //           acc   += selu(hidden @ fc_w + fc_b) * softmax(a_gate)[n]
    for (int n = 0; n < NHEADS; n++) {
        gemm_kernel<false, 1><<<dim3(16, 32, 1), blk>>>(
            ov + (size_t)n * HEAD_MK, w_o + (size_t)n * KSIZE * 2048, hidden,
            KSIZE, KSIZE, 2048, 2048,
            0LL, 0LL, 0LL, 0.f, gates + n, nullptr);
        gemm_kernel<false, 2><<<dim3(8, 32, 1), blk>>>(
            hidden, fc_w, acc,
            2048, 2048, HSIZE, HSIZE,
            0LL, 0LL, 0LL, 0.f, gates + 8 + n, fc_b);
    }

    // y = layernorm(acc + q) * gamma + beta
    ln_kernel<<<MROWS, 256>>>(acc, q, ln_g, ln_b, out_y);
}

// round 5
// speedup vs baseline: 2.8996x; 2.8996x over previous
#include <cuda_runtime.h>
#include <math.h>
#include <stdint.h>

// ---------------------------------------------------------------------------
// BranchedAttention: B=4, Q=S=1024, H=1024, N_HEADS=8, K_SIZE=V_SIZE=128
// Output: y [4,1024,1024] followed by attn [32,1024,1024] (float32)
// GEMMs: mma.sync m16n8k8 tf32, 4-stage cp.async pipeline.
// ---------------------------------------------------------------------------

#define NHEADS 8
#define BATCH  4
#define QLEN   1024
#define SLEN   1024
#define HSIZE  1024
#define KSIZE  128
#define MROWS  (BATCH * QLEN)           // 4096
#define HEAD_MK ((size_t)MROWS * KSIZE) // 524288
#define BQ_MK  ((size_t)QLEN * KSIZE)   // 131072
#define NSTAGES 4

// Scratch (device globals; allocation-free)
static __device__ float g_qh[(size_t)NHEADS * MROWS * KSIZE];
static __device__ float g_kh[(size_t)NHEADS * MROWS * KSIZE];
static __device__ float g_vh[(size_t)NHEADS * MROWS * KSIZE];
static __device__ float g_ov[(size_t)NHEADS * MROWS * KSIZE];
static __device__ float g_hidden[(size_t)NHEADS * MROWS * 2048]; // 268MB
static __device__ float g_fcout[(size_t)NHEADS * MROWS * HSIZE]; // 134MB
static __device__ float g_gates[16]; // [0..7]=softmax(k_gate), [8..15]=softmax(a_gate)

// ---------------------------------------------------------------------------
__global__ void gates_kernel(const float* __restrict__ kg, const float* __restrict__ ag) {
    if (threadIdx.x == 0) {
        float mk = -1e30f, ma = -1e30f;
        for (int i = 0; i < 8; i++) { mk = fmaxf(mk, kg[i]); ma = fmaxf(ma, ag[i]); }
        float ek[8], ea[8], sk = 0.f, sa = 0.f;
        for (int i = 0; i < 8; i++) {
            ek[i] = expf(kg[i] - mk); sk += ek[i];
            ea[i] = expf(ag[i] - ma); sa += ea[i];
        }
        for (int i = 0; i < 8; i++) {
            g_gates[i]     = ek[i] / sk;
            g_gates[8 + i] = ea[i] / sa;
        }
    }
}

// ---------------------------------------------------------------------------
__device__ __forceinline__ uint32_t f2tf(float x) {
    uint32_t r;
    asm("cvt.rna.tf32.f32 %0, %1;" : "=r"(r) : "f"(x));
    return r;
}

__device__ __forceinline__ void mma_tf32(float c[4],
                                         const uint32_t a[4],
                                         const uint32_t b[2]) {
    asm volatile(
        "mma.sync.aligned.m16n8k8.row.col.f32.tf32.tf32.f32 "
        "{%0,%1,%2,%3}, {%4,%5,%6,%7}, {%8,%9}, {%0,%1,%2,%3};"
        : "+f"(c[0]), "+f"(c[1]), "+f"(c[2]), "+f"(c[3])
        : "r"(a[0]), "r"(a[1]), "r"(a[2]), "r"(a[3]), "r"(b[0]), "r"(b[1]));
}

__device__ __forceinline__ void cp16(float* s, const float* g) {
    uint32_t sa = (uint32_t)__cvta_generic_to_shared(s);
    asm volatile("cp.async.cg.shared.global [%0], [%1], 16;" :: "r"(sa), "l"(g));
}
__device__ __forceinline__ void cp_commit() {
    asm volatile("cp.async.commit_group;");
}
template<int N>
__device__ __forceinline__ void cp_wait() {
    asm volatile("cp.async.wait_group %0;" :: "n"(N));
}

// ---------------------------------------------------------------------------
// GEMM body: C[tile] = op(A[M,K] * B), row-major, tile 128x128, 256 threads
// (8 warps 2x4, warp tile 64x32). 4-stage cp.async pipeline, k-chunk 16.
// TRANSB=false: B is [K,N]. TRANSB=true: B is [N,K] (C = A*B^T).
// EPI 0/1: C = alpha * AB     EPI 2: C = selu(AB + bias[col]) * alpha
// ---------------------------------------------------------------------------
template<bool TRANSB, int EPI>
__device__ __forceinline__ void gemm_body(
    const float* __restrict__ A, const float* __restrict__ B, float* __restrict__ C,
    int K, int lda, int ldb, int ldc, int m0b, int n0b,
    float alpha, const float* __restrict__ bias, float* smem)
{
    constexpr int A_ST = 128 * 20;
    constexpr int B_ST = TRANSB ? 128 * 20 : 16 * 136;
    float* Abase = smem;
    float* Bbase = smem + NSTAGES * A_ST;

    const int t    = threadIdx.x;
    const int lane = t & 31;
    const int warp = t >> 5;
    const int wm   = warp >> 2;
    const int wn   = warp & 3;
    const int g    = lane >> 2;
    const int tg   = lane & 3;

    const int pa_m = t >> 1;           // 0..127
    const int pa_k = (t & 1) << 3;     // 0 or 8
    const int pb_k = t >> 4;           // 0..15 (NN B)
    const int pb_n = (t & 15) << 3;    // 0..120

    const int niter = K >> 4;

    auto load_stage = [&](int s, int k0) {
        float* As = Abase + s * A_ST;
        const float* ap = A + (size_t)(m0b + pa_m) * lda + k0 + pa_k;
        cp16(&As[pa_m * 20 + pa_k],     ap);
        cp16(&As[pa_m * 20 + pa_k + 4], ap + 4);
        float* Bs = Bbase + s * B_ST;
        if (TRANSB) {
            const float* bp = B + (size_t)(n0b + pa_m) * ldb + k0 + pa_k;
            cp16(&Bs[pa_m * 20 + pa_k],     bp);
            cp16(&Bs[pa_m * 20 + pa_k + 4], bp + 4);
        } else {
            const float* bp = B + (size_t)(k0 + pb_k) * ldb + n0b + pb_n;
            cp16(&Bs[pb_k * 136 + pb_n],     bp);
            cp16(&Bs[pb_k * 136 + pb_n + 4], bp + 4);
        }
    };

    float acc[4][4][4];
#pragma unroll
    for (int mt = 0; mt < 4; mt++)
#pragma unroll
        for (int nt = 0; nt < 4; nt++)
#pragma unroll
            for (int r = 0; r < 4; r++) acc[mt][nt][r] = 0.f;

    // prologue: stages 0..NSTAGES-2
#pragma unroll
    for (int p = 0; p < NSTAGES - 1; p++) {
        if (p < niter) load_stage(p, p << 4);
        cp_commit();
    }

    for (int i = 0; i < niter; i++) {
        cp_wait<NSTAGES - 2>();
        __syncthreads();

        // prefetch stage i+NSTAGES-1 (overwrites stage (i-1)%4: all threads
        // passed the barrier above after finishing compute on it)
        {
            const int pi = i + NSTAGES - 1;
            if (pi < niter) load_stage(pi & (NSTAGES - 1), pi << 4);
            cp_commit();
        }

        const float* As = Abase + (i & (NSTAGES - 1)) * A_ST;
        const float* Bs = Bbase + (i & (NSTAGES - 1)) * B_ST;
#pragma unroll
        for (int ks = 0; ks < 2; ks++) {
            const int kb = ks << 3;
            uint32_t af[4][4];
#pragma unroll
            for (int mt = 0; mt < 4; mt++) {
                const int mr = wm * 64 + mt * 16 + g;
                af[mt][0] = f2tf(As[(mr)     * 20 + kb + tg]);
                af[mt][1] = f2tf(As[(mr + 8) * 20 + kb + tg]);
                af[mt][2] = f2tf(As[(mr)     * 20 + kb + tg + 4]);
                af[mt][3] = f2tf(As[(mr + 8) * 20 + kb + tg + 4]);
            }
            uint32_t bf[4][2];
#pragma unroll
            for (int nt = 0; nt < 4; nt++) {
                const int nc = wn * 32 + nt * 8 + g;
                if (TRANSB) {
                    bf[nt][0] = f2tf(Bs[nc * 20 + kb + tg]);
                    bf[nt][1] = f2tf(Bs[nc * 20 + kb + tg + 4]);
                } else {
                    bf[nt][0] = f2tf(Bs[(kb + tg)     * 136 + nc]);
                    bf[nt][1] = f2tf(Bs[(kb + tg + 4) * 136 + nc]);
                }
            }
#pragma unroll
            for (int mt = 0; mt < 4; mt++)
#pragma unroll
                for (int nt = 0; nt < 4; nt++)
                    mma_tf32(acc[mt][nt], af[mt], bf[nt]);
        }
    }

    // epilogue
#pragma unroll
    for (int mt = 0; mt < 4; mt++) {
        const int r0 = m0b + wm * 64 + mt * 16 + g;
#pragma unroll
        for (int nt = 0; nt < 4; nt++) {
            const int c0 = n0b + wn * 32 + nt * 8 + 2 * tg;
            float v0 = acc[mt][nt][0], v1 = acc[mt][nt][1];
            float v2 = acc[mt][nt][2], v3 = acc[mt][nt][3];
            if (EPI == 2) {
                const float b0 = bias[c0], b1 = bias[c0 + 1];
                v0 += b0; v1 += b1; v2 += b0; v3 += b1;
                v0 = (v0 > 0.f) ? 1.0507009873554805f * v0
                                : 1.7580993408473768f * (expf(v0) - 1.f);
                v1 = (v1 > 0.f) ? 1.0507009873554805f * v1
                                : 1.7580993408473768f * (expf(v1) - 1.f);
                v2 = (v2 > 0.f) ? 1.0507009873554805f * v2
                                : 1.7580993408473768f * (expf(v2) - 1.f);
                v3 = (v3 > 0.f) ? 1.0507009873554805f * v3
                                : 1.7580993408473768f * (expf(v3) - 1.f);
            }
            v0 *= alpha; v1 *= alpha; v2 *= alpha; v3 *= alpha;
            *(float2*)(C + (size_t)r0 * ldc + c0)       = make_float2(v0, v1);
            *(float2*)(C + (size_t)(r0 + 8) * ldc + c0) = make_float2(v2, v3);
        }
    }
}

// ---------------------------------------------------------------------------
template<bool TRANSB, int EPI>
__global__ void __launch_bounds__(256)
gemm_tc(const float* __restrict__ A, const float* __restrict__ B,
        float* __restrict__ C,
        int K, int lda, int ldb, int ldc,
        long long sA, long long sB, long long sC,
        float alpha_imm, const float* __restrict__ alpha_ptr,
        const float* __restrict__ bias)
{
    extern __shared__ float smem[];
    A += (long long)blockIdx.z * sA;
    B += (long long)blockIdx.z * sB;
    C += (long long)blockIdx.z * sC;
    const float alpha = (EPI == 0) ? alpha_imm : alpha_ptr[blockIdx.z];
    gemm_body<TRANSB, EPI>(A, B, C, K, lda, ldb, ldc,
                           blockIdx.y * 128, blockIdx.x * 128, alpha, bias, smem);
}

// Fused q/k/v projections: z = sel*8 + head, sel in {0:q,1:k,2:v}
__global__ void __launch_bounds__(256)
gemm_proj(const float* __restrict__ A0, const float* __restrict__ A1,
          const float* __restrict__ A2,
          const float* __restrict__ B0, const float* __restrict__ B1,
          const float* __restrict__ B2,
          float* __restrict__ C0, float* __restrict__ C1, float* __restrict__ C2)
{
    extern __shared__ float smem[];
    const int z = blockIdx.z;
    const int sel = z >> 3, head = z & 7;
    const float* A = (sel == 0) ? A0 : ((sel == 1) ? A1 : A2);
    const float* B = ((sel == 0) ? B0 : ((sel == 1) ? B1 : B2)) + (size_t)head * HSIZE * KSIZE;
    float* C = ((sel == 0) ? C0 : ((sel == 1) ? C1 : C2)) + (size_t)head * HEAD_MK;
    gemm_body<false, 0>(A, B, C, HSIZE, HSIZE, KSIZE, KSIZE,
                        blockIdx.y * 128, blockIdx.x * 128, 1.f, nullptr, smem);
}

// ---------------------------------------------------------------------------
// Block reductions (256 threads, 8 warps)
// ---------------------------------------------------------------------------
__device__ __forceinline__ float warp_sum(float v) {
#pragma unroll
    for (int o = 16; o > 0; o >>= 1) v += __shfl_xor_sync(0xffffffffu, v, o);
    return v;
}
__device__ __forceinline__ float warp_max(float v) {
#pragma unroll
    for (int o = 16; o > 0; o >>= 1) v = fmaxf(v, __shfl_xor_sync(0xffffffffu, v, o));
    return v;
}
__device__ __forceinline__ float block_sum(float v, float* sh) {
    v = warp_sum(v);
    __syncthreads();
    if ((threadIdx.x & 31) == 0) sh[threadIdx.x >> 5] = v;
    __syncthreads();
    if (threadIdx.x < 32) {
        float x = (threadIdx.x < 8) ? sh[threadIdx.x] : 0.f;
        x = warp_sum(x);
        if (threadIdx.x == 0) sh[0] = x;
    }
    __syncthreads();
    return sh[0];
}
__device__ __forceinline__ float block_max(float v, float* sh) {
    v = warp_max(v);
    __syncthreads();
    if ((threadIdx.x & 31) == 0) sh[threadIdx.x >> 5] = v;
    __syncthreads();
    if (threadIdx.x < 32) {
        float x = (threadIdx.x < 8) ? sh[threadIdx.x] : -1e30f;
        x = warp_max(x);
        if (threadIdx.x == 0) sh[0] = x;
    }
    __syncthreads();
    return sh[0];
}

// ---------------------------------------------------------------------------
// Row softmax over 1024 elements, in place. One block per row.
// ---------------------------------------------------------------------------
__global__ void __launch_bounds__(256) softmax_kernel(float* __restrict__ attn) {
    __shared__ float sh[8];
    float* row = attn + (size_t)blockIdx.x * SLEN;
    const int t = threadIdx.x;
    float4 v = *((float4*)row + t);
    float m = fmaxf(fmaxf(v.x, v.y), fmaxf(v.z, v.w));
    m = block_max(m, sh);
    v.x = __expf(v.x - m);
    v.y = __expf(v.y - m);
    v.z = __expf(v.z - m);
    v.w = __expf(v.w - m);
    float s = v.x + v.y + v.z + v.w;
    s = block_sum(s, sh);
    const float inv = 1.0f / s;
    v.x *= inv; v.y *= inv; v.z *= inv; v.w *= inv;
    *((float4*)row + t) = v;
}

// ---------------------------------------------------------------------------
// y = LayerNorm(sum_heads fcout[n] + residual). One block per row of 1024.
// ---------------------------------------------------------------------------
__global__ void __launch_bounds__(256)
ln_reduce_kernel(const float* __restrict__ fcout, const float* __restrict__ resid,
                 const float* __restrict__ gamma, const float* __restrict__ beta,
                 float* __restrict__ y)
{
    __shared__ float sh[8];
    const size_t off = (size_t)blockIdx.x * HSIZE;
    const int t = threadIdx.x;
    float4 x = *((const float4*)(resid + off) + t);
#pragma unroll
    for (int n = 0; n < NHEADS; n++) {
        float4 f = *((const float4*)(fcout + (size_t)n * MROWS * HSIZE + off) + t);
        x.x += f.x; x.y += f.y; x.z += f.z; x.w += f.w;
    }
    float s  = x.x + x.y + x.z + x.w;
    float ss = x.x * x.x + x.y * x.y + x.z * x.z + x.w * x.w;
    s = block_sum(s, sh);
    __syncthreads();
    ss = block_sum(ss, sh);
    const float mu   = s * (1.0f / HSIZE);
    const float var  = ss * (1.0f / HSIZE) - mu * mu;
    const float rstd = rsqrtf(var + 1e-6f);
    float4 gm = *((const float4*)gamma + t);
    float4 bt = *((const float4*)beta + t);
    float4 o;
    o.x = (x.x - mu) * rstd * gm.x + bt.x;
    o.y = (x.y - mu) * rstd * gm.y + bt.y;
    o.z = (x.z - mu) * rstd * gm.z + bt.z;
    o.w = (x.w - mu) * rstd * gm.w + bt.w;
    *((float4*)(y + off) + t) = o;
}

// ---------------------------------------------------------------------------
// Launcher
// ---------------------------------------------------------------------------
extern "C" void kernel_launch(void* const* d_in, const int* in_sizes, int n_in,
                              void* d_out, int out_size)
{
    const float* q      = (const float*)d_in[0];
    const float* k      = (const float*)d_in[1];
    const float* v      = (const float*)d_in[2];
    const float* w_q    = (const float*)d_in[3];
    const float* w_k    = (const float*)d_in[4];
    const float* w_v    = (const float*)d_in[5];
    const float* w_o    = (const float*)d_in[6];
    const float* a_gate = (const float*)d_in[7];
    const float* k_gate = (const float*)d_in[8];
    const float* fc_w   = (const float*)d_in[9];
    const float* fc_b   = (const float*)d_in[10];
    const float* ln_g   = (const float*)d_in[11];
    const float* ln_b   = (const float*)d_in[12];

    float* out_y    = (float*)d_out;
    float* out_attn = out_y + (size_t)BATCH * QLEN * HSIZE;

    float *qh, *kh, *vh, *ov, *hidden, *fcout, *gates;
    cudaGetSymbolAddress((void**)&qh,     g_qh);
    cudaGetSymbolAddress((void**)&kh,     g_kh);
    cudaGetSymbolAddress((void**)&vh,     g_vh);
    cudaGetSymbolAddress((void**)&ov,     g_ov);
    cudaGetSymbolAddress((void**)&hidden, g_hidden);
    cudaGetSymbolAddress((void**)&fcout,  g_fcout);
    cudaGetSymbolAddress((void**)&gates,  g_gates);

    // dynamic smem sizes: 4 stages of (A 128x20 + B)
    const int SMEM_NN = NSTAGES * (128 * 20 + 16 * 136) * 4;   // 75776
    const int SMEM_TR = NSTAGES * (128 * 20 + 128 * 20) * 4;   // 81920
    cudaFuncSetAttribute(gemm_proj,         cudaFuncAttributeMaxDynamicSharedMemorySize, SMEM_NN);
    cudaFuncSetAttribute(gemm_tc<true, 0>,  cudaFuncAttributeMaxDynamicSharedMemorySize, SMEM_TR);
    cudaFuncSetAttribute(gemm_tc<false, 0>, cudaFuncAttributeMaxDynamicSharedMemorySize, SMEM_NN);
    cudaFuncSetAttribute(gemm_tc<false, 1>, cudaFuncAttributeMaxDynamicSharedMemorySize, SMEM_NN);
    cudaFuncSetAttribute(gemm_tc<false, 2>, cudaFuncAttributeMaxDynamicSharedMemorySize, SMEM_NN);

    const dim3 blk(256);

    gates_kernel<<<1, 32>>>(k_gate, a_gate);

    // fused q/k/v projections: [4096,1024] @ [1024,128], z = sel*8 + head
    gemm_proj<<<dim3(1, 32, 24), blk, SMEM_NN>>>(
        q, k, v, w_q, w_k, w_v, qh, kh, vh);

    // scores: qh[z] @ kh[z]^T -> attn_raw [1024,1024], z = n*4+b (32)
    gemm_tc<true, 0><<<dim3(8, 8, 32), blk, SMEM_TR>>>(
        qh, kh, out_attn, KSIZE, KSIZE, KSIZE, SLEN,
        (long long)BQ_MK, (long long)BQ_MK, (long long)QLEN * SLEN,
        0.08838834764831843f, nullptr, nullptr);

    softmax_kernel<<<NHEADS * BATCH * QLEN, 256>>>(out_attn);

    // ov = attn @ vh : [1024,1024] @ [1024,128] per z (32)
    gemm_tc<false, 0><<<dim3(1, 8, 32), blk, SMEM_NN>>>(
        out_attn, vh, ov, SLEN, SLEN, KSIZE, KSIZE,
        (long long)QLEN * SLEN, (long long)BQ_MK, (long long)BQ_MK,
        1.f, nullptr, nullptr);

    // hidden[n] = (ov[n] @ w_o[n]) * softmax(k_gate)[n], batched z=8
    gemm_tc<false, 1><<<dim3(16, 32, 8), blk, SMEM_NN>>>(
        ov, w_o, hidden, KSIZE, KSIZE, 2048, 2048,
        (long long)HEAD_MK, (long long)KSIZE * 2048, (long long)MROWS * 2048,
        0.f, gates, nullptr);

    // fcout[n] = selu(hidden[n] @ fc_w + fc_b) * softmax(a_gate)[n], batched z=8
    gemm_tc<false, 2><<<dim3(8, 32, 8), blk, SMEM_NN>>>(
        hidden, fc_w, fcout, 2048, 2048, HSIZE, HSIZE,
        (long long)MROWS * 2048, 0LL, (long long)MROWS * HSIZE,
        0.f, gates + 8, fc_b);

    // y = layernorm(sum_n fcout[n] + q)
    ln_reduce_kernel<<<MROWS, 256>>>(fcout, q, ln_g, ln_b, out_y);
}